// round 13
// baseline (speedup 1.0000x reference)
#include <cuda_runtime.h>
#include <cuda_bf16.h>
#include <cstdint>

// B=256, NU=NL=QU=QL=64. One CTA = ONE batch row. 256 CTAs x 256 threads,
// ~89 KB smem -> 2 CTAs co-resident per SM (independent barrier domains),
// single wave over all 148 SMs. Cumulants truncated at c2.
#define THREADS 256

// ---------------- compile-time U table (pre-swizzled bf16) ------------------
// row r = l*2+n' holds u^(n'+1), u = ((l-m)/64)^2, at swizzled off r*128+m*2.
constexpr unsigned short f2bf_pos(double v) {
    if (v == 0.0) return 0;
    int e = 0;
    double m = v;
    while (m >= 2.0) { m *= 0.5; ++e; }
    while (m < 1.0)  { m *= 2.0; --e; }
    double frac = (m - 1.0) * 128.0;
    int fi = (int)frac;
    double rem = frac - (double)fi;
    int mant = fi;
    if (rem > 0.5) mant += 1;
    else if (rem == 0.5) mant += (fi & 1);
    int exp = e + 127;
    if (mant == 128) { mant = 0; exp += 1; }
    return (unsigned short)((exp << 7) | mant);
}
struct UTab { unsigned short v[8192]; };
constexpr UTab make_utab() {
    UTab t{};
    for (int r = 0; r < 128; ++r) {
        for (int m = 0; m < 64; ++m) {
            const int l = r >> 1, n = r & 1;
            const double d = (double)(l - m) / 64.0;
            const double u = d * d;
            const double val = n ? u * u : u;
            unsigned off = (unsigned)(r * 128 + m * 2);
            off ^= (off >> 3) & 0x70u;
            t.v[off >> 1] = f2bf_pos(val);
        }
    }
    return t;
}
__device__ const UTab g_U = make_utab();

// ---------------- smem byte offsets -----------------------------------------
#define SM_P    0u          // [64 k][64 bf16]                       8 KB
#define SM_U    8192u       // U: [128 rows l*2+n'][64 bf16]        16 KB
#define SM_TI   24576u      // T: 2 subtiles [64 j][128B], col 2k+n' 16 KB
#define SM_EB   40960u      // [64 l][66 f32]                       16.9 KB
#define SM_CI   57856u      // C: 2 subtiles [64 l][128B]           16 KB
#define SM_LS   74240u      // [64 l][65 f32]                       16.6 KB
#define SM_MISC 90880u      // a0inv: 64 f32
#define SMEM_TOTAL 91136u   // x2 CTAs = 178 KB < 228 KB

__device__ __forceinline__ uint32_t sw128(uint32_t o) { return o ^ ((o >> 3) & 0x70u); }

__device__ __forceinline__ uint32_t smem_u32(const void* p) {
    uint32_t a;
    asm("{ .reg .u64 t; cvta.to.shared.u64 t, %1; cvt.u32.u64 %0, t; }" : "=r"(a) : "l"(p));
    return a;
}

// m16n8k16 row.col bf16 -> f32 (sm_80-baseline PTX; HMMA on Blackwell)
__device__ __forceinline__ void mma16816(float acc[4], const uint32_t a[4],
                                         uint32_t b0, uint32_t b1) {
    asm volatile(
        "mma.sync.aligned.m16n8k16.row.col.f32.bf16.bf16.f32 "
        "{%0,%1,%2,%3}, {%4,%5,%6,%7}, {%8,%9}, {%0,%1,%2,%3};"
        : "+f"(acc[0]), "+f"(acc[1]), "+f"(acc[2]), "+f"(acc[3])
        : "r"(a[0]), "r"(a[1]), "r"(a[2]), "r"(a[3]), "r"(b0), "r"(b1));
}

__device__ __forceinline__ void ldmx4(uint32_t r[4], uint32_t addr) {
    asm volatile("ldmatrix.sync.aligned.m8n8.x4.shared.b16 {%0,%1,%2,%3}, [%4];"
                 : "=r"(r[0]), "=r"(r[1]), "=r"(r[2]), "=r"(r[3]) : "r"(addr));
}

#define CP_ASYNC16(dst, src) \
    asm volatile("cp.async.cg.shared.global [%0], [%1], 16;" :: "r"(dst), "l"(src))
#define CP_COMMIT() asm volatile("cp.async.commit_group;")
#define CP_WAIT0()  asm volatile("cp.async.wait_group 0;")

// ============================================================================
// Main fused kernel (single launch).
// ============================================================================
__global__ void __launch_bounds__(THREADS, 2)
drn_fused(const float* __restrict__ P, const float* __restrict__ weight,
          const float* __restrict__ bias_abs, const float* __restrict__ bias_q,
          const float* __restrict__ lam_abs, const float* __restrict__ lam_q,
          float* __restrict__ out)
{
    extern __shared__ __align__(16) char sm[];
    const uint32_t smb = smem_u32(sm);
    float* a0inv = (float*)(sm + SM_MISC);          // 64 floats

    const int tid = threadIdx.x;
    const int i   = blockIdx.x;

    // ---- kick off U-table copy (overlaps all setup below) ------------------
    {
        const unsigned char* gp = (const unsigned char*)g_U.v;
        const uint32_t off = (uint32_t)tid * 16;
        #pragma unroll
        for (int q = 0; q < 4; ++q)
            CP_ASYNC16(smb + SM_U + off + q * 4096u, gp + off + q * 4096u);
        CP_COMMIT();
    }

    // ---- build T: col 2k+n' holds t^(n'+1); one STS.32 per k ---------------
    {
        const int j = tid >> 2, kq = (tid & 3) * 16;
        const float4* wr = (const float4*)(weight + j * 64 + kq);
        #pragma unroll
        for (int h = 0; h < 4; ++h) {
            const float4 w = wr[h];
            const float tv[4] = {-w.x, -w.y, -w.z, -w.w};
            #pragma unroll
            for (int q = 0; q < 4; ++q) {
                const int k = kq + h * 4 + q;
                const float t = tv[q];
                const uint32_t off = (uint32_t)(k >> 5) * 8192u
                                   + (uint32_t)j * 128 + (uint32_t)(k & 31) * 4;
                const __nv_bfloat162 p = __floats2bfloat162_rn(t, t * t);
                *(unsigned*)(sm + SM_TI + sw128(off)) = *(const unsigned*)&p;
            }
        }
    }

    // ---- build EB: thread = (j, 16 l's) -------------------------------------
    {
        const int j = tid >> 2, l0 = (tid & 3) * 16;
        const float bq = bias_q[j], lq = lam_q[j];
        const float ba = bias_abs[j], la = lam_abs[j];
        float* eb = (float*)(sm + SM_EB);
        #pragma unroll
        for (int q = 0; q < 16; ++q) {
            const int l = l0 + q;
            const float sl = (float)l * (1.f / 64.f);
            const float dq = sl - lq, da = sl - la;
            eb[l * 66 + j] = -bq * dq * dq - ba * fabsf(da);
        }
    }

    // ---- fill P tile (bf16) + row sums (4 threads per row) -----------------
    {
        const int r = tid >> 2, qh = tid & 3;
        const float* src = P + ((size_t)i * 64 + r) * 64 + qh * 16;
        float s = 0.f;
        #pragma unroll
        for (int q = 0; q < 4; ++q) {
            const float4 f = ((const float4*)src)[q];
            s += f.x + f.y + f.z + f.w;
            const uint32_t off = (uint32_t)r * 128 + (qh * 16 + q * 4) * 2;
            *(__nv_bfloat162*)(sm + SM_P + sw128(off))     = __floats2bfloat162_rn(f.x, f.y);
            *(__nv_bfloat162*)(sm + SM_P + sw128(off + 4)) = __floats2bfloat162_rn(f.z, f.w);
        }
        s += __shfl_xor_sync(0xffffffffu, s, 1);
        s += __shfl_xor_sync(0xffffffffu, s, 2);
        if (qh == 0) a0inv[r] = 1.0f / s;
    }
    CP_WAIT0();
    __syncthreads();

    const int lane = tid & 31, wid = tid >> 5;
    const int g = lane >> 2, c = lane & 3;
    const int mw = wid & 1, nq = wid >> 1;   // M-half (32 k's), N-quarter

    // ldmatrix lane->address maps (relative byte offsets, pre-swizzle)
    const uint32_t aRow = (uint32_t)((lane & 7) + ((lane >> 3) & 1) * 8) * 128
                          + (uint32_t)(lane >> 4) * 16;
    const uint32_t bRow = (uint32_t)((lane & 7) + (lane >> 4) * 8) * 128
                          + (uint32_t)((lane >> 3) & 1) * 16;

    // Hoisted A fragments (P rows mw*32..+32)
    uint32_t afr[2][4][4];
    #pragma unroll
    for (int mt = 0; mt < 2; ++mt)
        #pragma unroll
        for (int ks = 0; ks < 4; ++ks)
            ldmx4(afr[mt][ks],
                  smb + SM_P + sw128((uint32_t)(mw * 32 + mt * 16) * 128 + aRow + ks * 32));

    // ============ GEMM1: M=64(k) x N=128(l,n') x K=64(m) =====================
    {
        float acc[2][4][4];
        #pragma unroll
        for (int mt = 0; mt < 2; ++mt)
            #pragma unroll
            for (int B = 0; B < 4; ++B)
                acc[mt][B][0] = acc[mt][B][1] = acc[mt][B][2] = acc[mt][B][3] = 0.f;

        #pragma unroll
        for (int ks = 0; ks < 4; ++ks) {
            uint32_t b0[4], b1[4];
            ldmx4(b0, smb + SM_U + sw128((uint32_t)(nq * 32) * 128 + bRow + ks * 32));
            ldmx4(b1, smb + SM_U + sw128((uint32_t)(nq * 32 + 16) * 128 + bRow + ks * 32));
            #pragma unroll
            for (int mt = 0; mt < 2; ++mt) {
                mma16816(acc[mt][0], afr[mt][ks], b0[0], b0[1]);
                mma16816(acc[mt][1], afr[mt][ks], b0[2], b0[3]);
                mma16816(acc[mt][2], afr[mt][ks], b1[0], b1[1]);
                mma16816(acc[mt][3], afr[mt][ks], b1[2], b1[3]);
            }
        }

        // epilogue: M1,M2 are IN-LANE (cols 2c,2c+1 = n'=0,1 at l=nq*16+B*4+c).
        const uint32_t cib = SM_CI + (uint32_t)mw * 8192u;
        #pragma unroll
        for (int mt = 0; mt < 2; ++mt) {
            const int kg = mw * 32 + mt * 16 + g;
            const float ai_g = a0inv[kg];
            const float ai_h = a0inv[kg + 8];
            #pragma unroll
            for (int B = 0; B < 4; ++B) {
                const float* a = acc[mt][B];
                const int l = nq * 16 + B * 4 + c;
                const float m1g = a[0] * ai_g, m2g = a[1] * ai_g;
                const float m1h = a[2] * ai_h, m2h = a[3] * ai_h;
                const float c2g = 0.5f * (m2g - m1g * m1g);
                const float c2h = 0.5f * (m2h - m1h * m1h);
                const __nv_bfloat162 pg = __floats2bfloat162_rn(m1g, c2g);
                const __nv_bfloat162 ph = __floats2bfloat162_rn(m1h, c2h);
                const uint32_t offg = (uint32_t)l * 128 + (uint32_t)(kg & 31) * 4;
                *(unsigned*)(sm + cib + sw128(offg))      = *(const unsigned*)&pg;
                *(unsigned*)(sm + cib + sw128(offg + 32)) = *(const unsigned*)&ph;
            }
        }
    }
    __syncthreads();

    // ============ GEMM2: M=64(l) x N=64(j) x K=128(k,n') =====================
    {
        float acc[2][2][4];
        #pragma unroll
        for (int mt = 0; mt < 2; ++mt)
            #pragma unroll
            for (int bk = 0; bk < 2; ++bk)
                acc[mt][bk][0] = acc[mt][bk][1] = acc[mt][bk][2] = acc[mt][bk][3] = 0.f;

        #pragma unroll
        for (int q = 0; q < 8; ++q) {
            const uint32_t s = (uint32_t)q >> 2, ks = (uint32_t)q & 3;
            uint32_t b[4];
            ldmx4(b, smb + SM_TI + s * 8192u
                     + sw128((uint32_t)(nq * 16) * 128 + bRow + ks * 32));
            #pragma unroll
            for (int mt = 0; mt < 2; ++mt) {
                uint32_t a[4];
                ldmx4(a, smb + SM_CI + s * 8192u
                         + sw128((uint32_t)(mw * 32 + mt * 16) * 128 + aRow + ks * 32));
                mma16816(acc[mt][0], a, b[0], b[1]);
                mma16816(acc[mt][1], a, b[2], b[3]);
            }
        }

        // epilogue: + EB table, stage to LS
        float* ls = (float*)(sm + SM_LS);
        const float* eb = (const float*)(sm + SM_EB);
        #pragma unroll
        for (int mt = 0; mt < 2; ++mt) {
            const int lA = mw * 32 + mt * 16 + g, lB = lA + 8;
            #pragma unroll
            for (int bk = 0; bk < 2; ++bk) {
                const float* a = acc[mt][bk];
                const int j0 = nq * 16 + bk * 8 + c * 2;
                const float2 eA = *(const float2*)&eb[lA * 66 + j0];
                const float2 eB = *(const float2*)&eb[lB * 66 + j0];
                ls[lA * 65 + j0]     = a[0] + eA.x;
                ls[lA * 65 + j0 + 1] = a[1] + eA.y;
                ls[lB * 65 + j0]     = a[2] + eB.x;
                ls[lB * 65 + j0 + 1] = a[3] + eB.y;
            }
        }
    }
    __syncthreads();

    // ====== softmax over l (no max pass: |logits| <= ~4, fp32-safe) =========
    {
        const float* ls = (const float*)(sm + SM_LS);
        const int j = tid >> 2, h = tid & 3;
        float v[16], s = 0.f;
        #pragma unroll
        for (int q = 0; q < 16; ++q) {
            v[q] = __expf(ls[(h * 16 + q) * 65 + j]);
            s += v[q];
        }
        s += __shfl_xor_sync(0xffffffffu, s, 1);
        s += __shfl_xor_sync(0xffffffffu, s, 2);
        const float inv = 1.0f / s;
        float4* ob = (float4*)(out + ((size_t)i * 64 + j) * 64 + h * 16);
        #pragma unroll
        for (int q = 0; q < 4; ++q)
            ob[q] = make_float4(v[4 * q] * inv, v[4 * q + 1] * inv,
                                v[4 * q + 2] * inv, v[4 * q + 3] * inv);
    }
}

// ---------------------------------------------------------------------------
extern "C" void kernel_launch(void* const* d_in, const int* in_sizes, int n_in,
                              void* d_out, int out_size)
{
    const float* P        = (const float*)d_in[0];
    const float* weight   = (const float*)d_in[1];
    const float* bias_abs = (const float*)d_in[2];
    const float* bias_q   = (const float*)d_in[3];
    const float* lam_abs  = (const float*)d_in[4];
    const float* lam_q    = (const float*)d_in[5];
    float* out = (float*)d_out;

    cudaFuncSetAttribute(drn_fused, cudaFuncAttributeMaxDynamicSharedMemorySize,
                         SMEM_TOTAL);
    drn_fused<<<256, THREADS, SMEM_TOTAL>>>(P, weight, bias_abs, bias_q,
                                            lam_abs, lam_q, out);
}

// round 14
// speedup vs baseline: 1.2119x; 1.2119x over previous
#include <cuda_runtime.h>
#include <cuda_bf16.h>
#include <cstdint>

// B=256, NU=NL=QU=QL=64. One CTA = 2 batch rows, 2 independent warp-groups
// (8 warps each, named barriers). 128 CTAs x 512 threads, single launch.
// Cumulants truncated at c2; softmax reduced in registers (no LS transpose).
#define THREADS 512

// ---------------- compile-time U table (pre-swizzled bf16) ------------------
// row r = l*2+n' holds u^(n'+1), u = ((l-m)/64)^2, at swizzled off r*128+m*2.
constexpr unsigned short f2bf_pos(double v) {
    if (v == 0.0) return 0;
    int e = 0;
    double m = v;
    while (m >= 2.0) { m *= 0.5; ++e; }
    while (m < 1.0)  { m *= 2.0; --e; }
    double frac = (m - 1.0) * 128.0;
    int fi = (int)frac;
    double rem = frac - (double)fi;
    int mant = fi;
    if (rem > 0.5) mant += 1;
    else if (rem == 0.5) mant += (fi & 1);
    int exp = e + 127;
    if (mant == 128) { mant = 0; exp += 1; }
    return (unsigned short)((exp << 7) | mant);
}
struct UTab { unsigned short v[8192]; };
constexpr UTab make_utab() {
    UTab t{};
    for (int r = 0; r < 128; ++r) {
        for (int m = 0; m < 64; ++m) {
            const int l = r >> 1, n = r & 1;
            const double d = (double)(l - m) / 64.0;
            const double u = d * d;
            const double val = n ? u * u : u;
            unsigned off = (unsigned)(r * 128 + m * 2);
            off ^= (off >> 3) & 0x70u;
            t.v[off >> 1] = f2bf_pos(val);
        }
    }
    return t;
}
__device__ const UTab g_U = make_utab();

// ---------------- smem byte offsets -----------------------------------------
#define SM_P    0u          // [128 rows (ii,k)][64 bf16]           16 KB
#define SM_U    16384u      // U: [128 rows l*2+n'][64 bf16]        16 KB
#define SM_TI   32768u      // T: 2 subtiles [64 j][128B], col 2k+n' 16 KB
#define SM_EB   49152u      // [64 l][66 f32]                       16.9 KB
#define SM_CI   66048u      // C: 2 groups x 2 subtiles [64 l][128B] 32 KB
#define SM_DN   98816u      // denom partials: 2 groups x [2 mw][64 f32] 1 KB
#define SM_MISC 99840u      // a0inv: 128 f32
#define SMEM_TOTAL 100352u

__device__ __forceinline__ uint32_t sw128(uint32_t o) { return o ^ ((o >> 3) & 0x70u); }

__device__ __forceinline__ uint32_t smem_u32(const void* p) {
    uint32_t a;
    asm("{ .reg .u64 t; cvta.to.shared.u64 t, %1; cvt.u32.u64 %0, t; }" : "=r"(a) : "l"(p));
    return a;
}

// m16n8k16 row.col bf16 -> f32 (sm_80-baseline PTX; HMMA on Blackwell)
__device__ __forceinline__ void mma16816(float acc[4], const uint32_t a[4],
                                         uint32_t b0, uint32_t b1) {
    asm volatile(
        "mma.sync.aligned.m16n8k16.row.col.f32.bf16.bf16.f32 "
        "{%0,%1,%2,%3}, {%4,%5,%6,%7}, {%8,%9}, {%0,%1,%2,%3};"
        : "+f"(acc[0]), "+f"(acc[1]), "+f"(acc[2]), "+f"(acc[3])
        : "r"(a[0]), "r"(a[1]), "r"(a[2]), "r"(a[3]), "r"(b0), "r"(b1));
}

__device__ __forceinline__ void ldmx4(uint32_t r[4], uint32_t addr) {
    asm volatile("ldmatrix.sync.aligned.m8n8.x4.shared.b16 {%0,%1,%2,%3}, [%4];"
                 : "=r"(r[0]), "=r"(r[1]), "=r"(r[2]), "=r"(r[3]) : "r"(addr));
}

#define CP_ASYNC16(dst, src) \
    asm volatile("cp.async.cg.shared.global [%0], [%1], 16;" :: "r"(dst), "l"(src))
#define CP_COMMIT() asm volatile("cp.async.commit_group;")
#define CP_WAIT0()  asm volatile("cp.async.wait_group 0;")
// group barrier: named barrier id (1 or 2), 256 threads
#define BARG(id) asm volatile("bar.sync %0, %1;" :: "r"(id), "r"(256) : "memory")

// ============================================================================
// Main fused kernel (single launch).
// ============================================================================
__global__ void __launch_bounds__(THREADS, 1)
drn_fused(const float* __restrict__ P, const float* __restrict__ weight,
          const float* __restrict__ bias_abs, const float* __restrict__ bias_q,
          const float* __restrict__ lam_abs, const float* __restrict__ lam_q,
          float* __restrict__ out)
{
    extern __shared__ __align__(16) char sm[];
    const uint32_t smb = smem_u32(sm);
    float* a0inv = (float*)(sm + SM_MISC);          // 128 floats

    const int tid = threadIdx.x;
    const int i0  = blockIdx.x * 2;

    // ---- hoist ALL global loads to the top (latency overlaps setup) --------
    const int pr_ = tid >> 2, pq_ = tid & 3;        // P: 4 threads per row
    const float* psrc = P + ((size_t)(i0 + (pr_ >> 6)) * 64 + (pr_ & 63)) * 64 + pq_ * 16;
    float4 pf[4];
    #pragma unroll
    for (int q = 0; q < 4; ++q) pf[q] = ((const float4*)psrc)[q];

    const int jT = tid >> 3, kqT = (tid & 7) * 8;   // T: 8 k's per thread
    const float4* wr = (const float4*)(weight + jT * 64 + kqT);
    const float4 w0 = wr[0], w1 = wr[1];
    const float bq_ = bias_q[jT], lq_ = lam_q[jT];
    const float ba_ = bias_abs[jT], la_ = lam_abs[jT];

    // ---- U-table copy (async, overlaps everything) -------------------------
    {
        const unsigned char* gp = (const unsigned char*)g_U.v;
        const uint32_t off = (uint32_t)tid * 16;
        CP_ASYNC16(smb + SM_U + off, gp + off);
        CP_ASYNC16(smb + SM_U + off + 8192u, gp + off + 8192u);
        CP_COMMIT();
    }

    // ---- build T: col 2k+n' holds t^(n'+1); one STS.32 per k ---------------
    {
        const float tv[8] = {-w0.x, -w0.y, -w0.z, -w0.w, -w1.x, -w1.y, -w1.z, -w1.w};
        #pragma unroll
        for (int q = 0; q < 8; ++q) {
            const int k = kqT + q;
            const float t = tv[q];
            const uint32_t off = (uint32_t)(k >> 5) * 8192u
                               + (uint32_t)jT * 128 + (uint32_t)(k & 31) * 4;
            const __nv_bfloat162 p = __floats2bfloat162_rn(t, t * t);
            *(unsigned*)(sm + SM_TI + sw128(off)) = *(const unsigned*)&p;
        }
    }

    // ---- build EB: thread = (jT, 8 l's) --------------------------------------
    {
        const int l0 = (tid & 7) * 8;
        float* eb = (float*)(sm + SM_EB);
        #pragma unroll
        for (int q = 0; q < 8; ++q) {
            const int l = l0 + q;
            const float sl = (float)l * (1.f / 64.f);
            const float dq = sl - lq_, da = sl - la_;
            eb[l * 66 + jT] = -bq_ * dq * dq - ba_ * fabsf(da);
        }
    }

    // ---- fill P tile (bf16) + row sums --------------------------------------
    {
        float s = 0.f;
        #pragma unroll
        for (int q = 0; q < 4; ++q) {
            const float4 f = pf[q];
            s += f.x + f.y + f.z + f.w;
            const uint32_t off = (uint32_t)pr_ * 128 + (pq_ * 16 + q * 4) * 2;
            *(__nv_bfloat162*)(sm + SM_P + sw128(off))     = __floats2bfloat162_rn(f.x, f.y);
            *(__nv_bfloat162*)(sm + SM_P + sw128(off + 4)) = __floats2bfloat162_rn(f.z, f.w);
        }
        s += __shfl_xor_sync(0xffffffffu, s, 1);
        s += __shfl_xor_sync(0xffffffffu, s, 2);
        if (pq_ == 0) a0inv[pr_] = 1.0f / s;
    }
    CP_WAIT0();
    __syncthreads();   // the ONLY full-CTA barrier; groups diverge after this

    const int lane = tid & 31, wid = tid >> 5;
    const int g = lane >> 2, c = lane & 3;
    const int g2   = wid >> 3;            // warp-group = batch row
    const int barid = 1 + g2;
    const int wid8 = wid & 7;
    const int mw = wid8 & 1, nq = wid8 >> 1;   // M-half (32 k's / l's), N-quarter
    const int mr = g2 * 64 + mw * 32;          // P-row base for GEMM1

    // ldmatrix lane->address maps (relative byte offsets, pre-swizzle)
    const uint32_t aRow = (uint32_t)((lane & 7) + ((lane >> 3) & 1) * 8) * 128
                          + (uint32_t)(lane >> 4) * 16;
    const uint32_t bRow = (uint32_t)((lane & 7) + (lane >> 4) * 8) * 128
                          + (uint32_t)((lane >> 3) & 1) * 16;

    // Hoisted A fragments (P tile rows mr..mr+32)
    uint32_t afr[2][4][4];
    #pragma unroll
    for (int mt = 0; mt < 2; ++mt)
        #pragma unroll
        for (int ks = 0; ks < 4; ++ks)
            ldmx4(afr[mt][ks],
                  smb + SM_P + sw128((uint32_t)(mr + mt * 16) * 128 + aRow + ks * 32));

    // ============ GEMM1: M=64(k) x N=128(l,n') x K=64(m) =====================
    {
        float acc[2][4][4];
        #pragma unroll
        for (int mt = 0; mt < 2; ++mt)
            #pragma unroll
            for (int B = 0; B < 4; ++B)
                acc[mt][B][0] = acc[mt][B][1] = acc[mt][B][2] = acc[mt][B][3] = 0.f;

        #pragma unroll
        for (int ks = 0; ks < 4; ++ks) {
            uint32_t b0[4], b1[4];
            ldmx4(b0, smb + SM_U + sw128((uint32_t)(nq * 32) * 128 + bRow + ks * 32));
            ldmx4(b1, smb + SM_U + sw128((uint32_t)(nq * 32 + 16) * 128 + bRow + ks * 32));
            #pragma unroll
            for (int mt = 0; mt < 2; ++mt) {
                mma16816(acc[mt][0], afr[mt][ks], b0[0], b0[1]);
                mma16816(acc[mt][1], afr[mt][ks], b0[2], b0[3]);
                mma16816(acc[mt][2], afr[mt][ks], b1[0], b1[1]);
                mma16816(acc[mt][3], afr[mt][ks], b1[2], b1[3]);
            }
        }

        // epilogue: M1,M2 are IN-LANE (cols 2c,2c+1 = n'=0,1 at l=nq*16+B*4+c).
        const uint32_t cib = SM_CI + (uint32_t)g2 * 16384u + (uint32_t)mw * 8192u;
        #pragma unroll
        for (int mt = 0; mt < 2; ++mt) {
            const int kg = mw * 32 + mt * 16 + g;
            const float ai_g = a0inv[g2 * 64 + kg];
            const float ai_h = a0inv[g2 * 64 + kg + 8];
            #pragma unroll
            for (int B = 0; B < 4; ++B) {
                const float* a = acc[mt][B];
                const int l = nq * 16 + B * 4 + c;
                const float m1g = a[0] * ai_g, m2g = a[1] * ai_g;
                const float m1h = a[2] * ai_h, m2h = a[3] * ai_h;
                const float c2g = 0.5f * (m2g - m1g * m1g);
                const float c2h = 0.5f * (m2h - m1h * m1h);
                const __nv_bfloat162 pg = __floats2bfloat162_rn(m1g, c2g);
                const __nv_bfloat162 ph = __floats2bfloat162_rn(m1h, c2h);
                const uint32_t offg = (uint32_t)l * 128 + (uint32_t)(kg & 31) * 4;
                *(unsigned*)(sm + cib + sw128(offg))      = *(const unsigned*)&pg;
                *(unsigned*)(sm + cib + sw128(offg + 32)) = *(const unsigned*)&ph;
            }
        }
    }
    BARG(barid);

    // ============ GEMM2 + register softmax ===================================
    {
        float acc[2][2][4];
        #pragma unroll
        for (int mt = 0; mt < 2; ++mt)
            #pragma unroll
            for (int bk = 0; bk < 2; ++bk)
                acc[mt][bk][0] = acc[mt][bk][1] = acc[mt][bk][2] = acc[mt][bk][3] = 0.f;

        #pragma unroll
        for (int q = 0; q < 8; ++q) {
            const uint32_t s = (uint32_t)q >> 2, ks = (uint32_t)q & 3;
            uint32_t b[4];
            ldmx4(b, smb + SM_TI + s * 8192u
                     + sw128((uint32_t)(nq * 16) * 128 + bRow + ks * 32));
            #pragma unroll
            for (int mt = 0; mt < 2; ++mt) {
                uint32_t a[4];
                ldmx4(a, smb + SM_CI + (uint32_t)g2 * 16384u + s * 8192u
                         + sw128((uint32_t)(mw * 32 + mt * 16) * 128 + aRow + ks * 32));
                mma16816(acc[mt][0], a, b[0], b[1]);
                mma16816(acc[mt][1], a, b[2], b[3]);
            }
        }

        // ---- epilogue: exp(logit + EB) in registers; reduce over l ---------
        // acc[mt][bk]: rows lA=mw*32+mt*16+g, lB=lA+8; cols j0=nq*16+bk*8+c*2, j0+1.
        const float* eb = (const float*)(sm + SM_EB);
        float ev[2][2][4];
        float sj[2][2] = {{0.f, 0.f}, {0.f, 0.f}};   // [bk][pair] partial sums
        #pragma unroll
        for (int mt = 0; mt < 2; ++mt) {
            const int lA = mw * 32 + mt * 16 + g, lB = lA + 8;
            #pragma unroll
            for (int bk = 0; bk < 2; ++bk) {
                const float* a = acc[mt][bk];
                const int j0 = nq * 16 + bk * 8 + c * 2;
                const float2 eA = *(const float2*)&eb[lA * 66 + j0];
                const float2 eB = *(const float2*)&eb[lB * 66 + j0];
                ev[mt][bk][0] = __expf(a[0] + eA.x);
                ev[mt][bk][1] = __expf(a[1] + eA.y);
                ev[mt][bk][2] = __expf(a[2] + eB.x);
                ev[mt][bk][3] = __expf(a[3] + eB.y);
                sj[bk][0] += ev[mt][bk][0] + ev[mt][bk][2];
                sj[bk][1] += ev[mt][bk][1] + ev[mt][bk][3];
            }
        }
        // reduce over g (lane bits 2..4) -> sum over this warp's 32 l's
        #pragma unroll
        for (int bk = 0; bk < 2; ++bk)
            #pragma unroll
            for (int pr = 0; pr < 2; ++pr) {
                float s = sj[bk][pr];
                s += __shfl_xor_sync(0xffffffffu, s, 4);
                s += __shfl_xor_sync(0xffffffffu, s, 8);
                s += __shfl_xor_sync(0xffffffffu, s, 16);
                sj[bk][pr] = s;
            }
        // exchange the mw-halves through smem
        float* D = (float*)(sm + SM_DN + (uint32_t)g2 * 512u);
        if (g == 0) {
            #pragma unroll
            for (int bk = 0; bk < 2; ++bk)
                #pragma unroll
                for (int pr = 0; pr < 2; ++pr)
                    D[mw * 64 + nq * 16 + bk * 8 + c * 2 + pr] = sj[bk][pr];
        }
        BARG(barid);
        float inv[2][2];
        #pragma unroll
        for (int bk = 0; bk < 2; ++bk)
            #pragma unroll
            for (int pr = 0; pr < 2; ++pr)
                inv[bk][pr] = 1.0f / (sj[bk][pr]
                              + D[(mw ^ 1) * 64 + nq * 16 + bk * 8 + c * 2 + pr]);
        // write out: out[(i0+g2), j, l]
        float* ob = out + (size_t)(i0 + g2) * 4096;
        #pragma unroll
        for (int mt = 0; mt < 2; ++mt) {
            const int lA = mw * 32 + mt * 16 + g, lB = lA + 8;
            #pragma unroll
            for (int bk = 0; bk < 2; ++bk) {
                const int j0 = nq * 16 + bk * 8 + c * 2;
                ob[j0 * 64 + lA]       = ev[mt][bk][0] * inv[bk][0];
                ob[(j0 + 1) * 64 + lA] = ev[mt][bk][1] * inv[bk][1];
                ob[j0 * 64 + lB]       = ev[mt][bk][2] * inv[bk][0];
                ob[(j0 + 1) * 64 + lB] = ev[mt][bk][3] * inv[bk][1];
            }
        }
    }
}

// ---------------------------------------------------------------------------
extern "C" void kernel_launch(void* const* d_in, const int* in_sizes, int n_in,
                              void* d_out, int out_size)
{
    const float* P        = (const float*)d_in[0];
    const float* weight   = (const float*)d_in[1];
    const float* bias_abs = (const float*)d_in[2];
    const float* bias_q   = (const float*)d_in[3];
    const float* lam_abs  = (const float*)d_in[4];
    const float* lam_q    = (const float*)d_in[5];
    float* out = (float*)d_out;

    cudaFuncSetAttribute(drn_fused, cudaFuncAttributeMaxDynamicSharedMemorySize,
                         SMEM_TOTAL);
    drn_fused<<<128, THREADS, SMEM_TOTAL>>>(P, weight, bias_abs, bias_q,
                                            lam_abs, lam_q, out);
}